// round 3
// baseline (speedup 1.0000x reference)
#include <cuda_runtime.h>
#include <cstdint>

// T=4 tables, E=1,000,000 rows/table, D=128 dims, B=8192 bags, L=32 bag length
// indices: [T, B, L] (int32 OR int64 — detected at runtime)
// weights: fp32 [T, E, D]; output: fp32 [B, T*D]
// out[b, t*D + d] = sum_l weights[t, indices[t,b,l], d]

#define T_TABLES 4
#define E_ROWS   1000000
#define D_DIM    128
#define B_BATCH  8192
#define L_BAG    32

// 1 = indices are int64, 0 = int32. Set by probe kernel each launch (deterministic).
__device__ int g_idx_is64;

__global__ void probe_idx_dtype(const long long* __restrict__ idx)
{
    if (threadIdx.x == 0 && blockIdx.x == 0) {
        int ok64 = 1;
        // If data is really int32, the int64 view's hi-words are random row ids
        // in [0,1M); the chance all 128 probed values land in [0,E) is ~0.
        for (int i = 0; i < 128; ++i) {
            long long v = idx[i];
            if (v < 0 || v >= E_ROWS) { ok64 = 0; break; }
        }
        g_idx_is64 = ok64;
    }
}

// One warp per bag b, iterating over the 4 tables in phase-locked order.
// 8192 warps = 1024 blocks x 8 warps = exactly one wave on 148 SMs, so all
// resident warps stream the SAME table's ~131MB footprint concurrently,
// maximizing L2 capture of repeated rows. __syncthreads() between table
// phases keeps blocks phase-aligned; single accumulator (stored per phase
// with streaming st.cs) keeps regs low enough for 56 warps/SM residency.
__global__ __launch_bounds__(256) void embbag_kernel(
    const void*  __restrict__ indices_raw,   // [T*B*L] int32 or int64
    const float* __restrict__ weights,       // [T*E*D]
    float*       __restrict__ out)           // [B*T*D]
{
    const int lane = threadIdx.x & 31;
    const int b    = blockIdx.x * 8 + (threadIdx.x >> 5);   // 0..8191, exact

    const int is64 = g_idx_is64;
    const float4* __restrict__ wf4 = reinterpret_cast<const float4*>(weights);
    float4* __restrict__ of4 =
        reinterpret_cast<float4*>(out) + (size_t)b * (T_TABLES * D_DIM / 4);

    #pragma unroll 1
    for (int t = 0; t < T_TABLES; ++t) {
        // Each lane loads one of the 32 bag indices (coalesced, streaming).
        const size_t idx_off = ((size_t)t * B_BATCH + b) * L_BAG + lane;
        long long my_idx;
        if (is64) {
            my_idx = __ldcs(((const long long*)indices_raw) + idx_off);
        } else {
            my_idx = (long long)__ldcs(((const int*)indices_raw) + idx_off);
        }

        const float4* __restrict__ wbase = wf4 + (size_t)t * E_ROWS * (D_DIM / 4);

        float4 acc = make_float4(0.f, 0.f, 0.f, 0.f);
        #pragma unroll
        for (int l = 0; l < L_BAG; ++l) {
            const long long row = __shfl_sync(0xffffffffu, my_idx, l);
            const float4 v = __ldg(wbase + (size_t)row * (D_DIM / 4) + lane);
            acc.x += v.x; acc.y += v.y; acc.z += v.z; acc.w += v.w;
        }

        // Streaming store: output is never re-read; don't pollute L2.
        __stcs(of4 + t * (D_DIM / 4) + lane, acc);

        // Keep the block phase-aligned on the same table for L2 locality.
        __syncthreads();
    }
}

extern "C" void kernel_launch(void* const* d_in, const int* in_sizes, int n_in,
                              void* d_out, int out_size)
{
    // Identify inputs by element count (robust to metadata ordering):
    // indices: T*B*L = 1,048,576 ; weights: T*E*D = 512,000,000
    const void*  indices = d_in[0];
    const float* weights = (const float*)d_in[1];
    if (n_in >= 2) {
        long long s0 = in_sizes[0], s1 = in_sizes[1];
        if (s0 > s1) {
            weights = (const float*)d_in[0];
            indices = d_in[1];
        }
    }
    float* out = (float*)d_out;

    probe_idx_dtype<<<1, 32>>>((const long long*)indices);

    const int blocks  = B_BATCH / 8;   // 1024 blocks x 8 warps = 8192 warps
    const int threads = 256;
    embbag_kernel<<<blocks, threads>>>(indices, weights, out);
}